// round 7
// baseline (speedup 1.0000x reference)
#include <cuda_runtime.h>
#include <cuda_bf16.h>
#include <cstdint>

// ---------------- Problem constants ----------------
#define N_ROWS   2048
#define DIM      256
#define T_TRK    256
#define NCOLS_XY 16384             // T*Q
#define BM       128
#define BN       128               // per half-tile; each block does 2 halves
#define NGRP_XY  (NCOLS_XY / 256)  // 64 column groups (2 tiles each)
#define NGRP_XX  (N_ROWS   / 256)  // 8
#define NGRP     (NGRP_XY + NGRP_XX) // 72
#define KCHUNK   32                // bf16 per K chunk (64B rows)
#define NCHUNK   (DIM / KCHUNK)    // 8
#define NCHNK_FIN 32               // finalize blocks (64 rows each)

// ---------------- Dynamic SMEM layout ----------------
#define A_BYTES      (BM * DIM * 2)        // 65536: full A tile, 8 chunks of 8KB
#define B_STAGE      (BN * KCHUNK * 2)     // 8192
#define OFF_A    0
#define OFF_B    A_BYTES                   // 2 stages
#define OFF_CTRK (OFF_B + 2 * B_STAGE)     // 256 ints
#define OFF_RTID (OFF_CTRK + 1024)         // 128 ints
#define OFF_REDT (OFF_RTID + 512)          // 256 floats
#define OFF_REDP (OFF_REDT + 1024)         // 256 floats
#define SMEM_BYTES (OFF_REDP + 1024)       // 85504

// ---------------- Device scratch ----------------
static __device__ __nv_bfloat16 g_xb[N_ROWS * DIM];
static __device__ __nv_bfloat16 g_yb[NCOLS_XY * DIM];
static __device__ float g_tot[NGRP * N_ROWS];
static __device__ float g_pos[NGRP * N_ROWS];
static __device__ float g_diag[N_ROWS];
static __device__ float g_pnum[NCHNK_FIN * T_TRK];   // [chunk][track] coalesced
static __device__ float g_pden[NCHNK_FIN * T_TRK];
static __device__ int   g_pcnt[NCHNK_FIN * T_TRK];
static __device__ int   g_tick;

// ---------------- PTX helpers (baseline sm_80+, legal on plain sm_103) ----
__device__ __forceinline__ uint32_t smem_u32(const void* p) {
    uint32_t a;
    asm("{ .reg .u64 t; cvta.to.shared.u64 t, %1; cvt.u32.u64 %0, t; }" : "=r"(a) : "l"(p));
    return a;
}
__device__ __forceinline__ void cp_async16(uint32_t dst, const void* src) {
    asm volatile("cp.async.cg.shared.global [%0], [%1], 16;" :: "r"(dst), "l"(src));
}
#define CP_COMMIT() asm volatile("cp.async.commit_group;" ::: "memory")
#define CP_WAIT(n)  asm volatile("cp.async.wait_group %0;" :: "n"(n) : "memory")

__device__ __forceinline__ void ldsm4(uint32_t r[4], uint32_t addr) {
    asm volatile("ldmatrix.sync.aligned.m8n8.x4.shared.b16 {%0,%1,%2,%3}, [%4];"
                 : "=r"(r[0]), "=r"(r[1]), "=r"(r[2]), "=r"(r[3]) : "r"(addr));
}
__device__ __forceinline__ void mma16816(float c[4], const uint32_t a[4], const uint32_t b[2]) {
    asm volatile(
        "mma.sync.aligned.m16n8k16.row.col.f32.bf16.bf16.f32 "
        "{%0,%1,%2,%3}, {%4,%5,%6,%7}, {%8,%9}, {%0,%1,%2,%3};"
        : "+f"(c[0]), "+f"(c[1]), "+f"(c[2]), "+f"(c[3])
        : "r"(a[0]), "r"(a[1]), "r"(a[2]), "r"(a[3]), "r"(b[0]), "r"(b[1]));
}

// ---------------- fp32 -> bf16 conversion (x and y in one launch) -------------
#define NX4 (N_ROWS * DIM / 4)      // 131072
#define NY4 (NCOLS_XY * DIM / 4)    // 1048576
__global__ void to_bf16_all(const float* __restrict__ x, const float* __restrict__ y)
{
    int i = blockIdx.x * blockDim.x + threadIdx.x;
    if (i == 0) g_tick = 0;                         // reset finalize ticket each call
    const float* s; __nv_bfloat16* d; int j;
    if (i < NX4) { s = x; d = g_xb; j = i; }
    else if (i < NX4 + NY4) { s = y; d = g_yb; j = i - NX4; }
    else return;
    float4 v = reinterpret_cast<const float4*>(s)[j];
    __nv_bfloat162* o = reinterpret_cast<__nv_bfloat162*>(d);
    o[j * 2 + 0] = __floats2bfloat162_rn(v.x, v.y);
    o[j * 2 + 1] = __floats2bfloat162_rn(v.z, v.w);
}

// ---------------- Fused HMMA GEMM + exp + row reductions ----------------
// grid (16, 72): blockIdx.y < 64 -> xy groups (512B of y cols), else xx groups.
// A tile (128x256) resident in smem for both halves; B double-buffered per chunk.
__global__ __launch_bounds__(256, 2)
void gemm_mma(const int* __restrict__ trk)
{
    extern __shared__ char smem[];
    const uint32_t sA = smem_u32(smem) + OFF_A;
    const uint32_t sB = smem_u32(smem) + OFF_B;
    int*   colTrkS = (int*)(smem + OFF_CTRK);
    int*   rowTidS = (int*)(smem + OFF_RTID);
    float* redT    = (float*)(smem + OFF_REDT);
    float* redP    = (float*)(smem + OFF_REDP);

    const int tid = threadIdx.x;
    const int wid = tid >> 5;
    const int lid = tid & 31;
    const int wm = wid & 3;      // warp m: rows wm*32..+31
    const int wn = wid >> 2;     // warp n: cols wn*64..+63

    const int bx = blockIdx.x;
    const int cg = blockIdx.y;                 // column group 0..71
    const bool isXX = (cg >= NGRP_XY);
    const int rowBase = bx * BM;
    const int colBaseGrp = isXX ? (cg - NGRP_XY) * 256 : cg * 256;
    const __nv_bfloat16* Bsrc = isXX ? g_xb : g_yb;

    // col tracks for both halves (xy: (colBaseGrp+j)&255 == j)
    colTrkS[tid] = isXX ? trk[colBaseGrp + tid] : tid;
    if (tid < BM) rowTidS[tid] = trk[rowBase + tid];

    // ---- ldmatrix lane offsets (SW64 within each 8KB A chunk / B stage) ----
    uint32_t aOff[2][2];
    #pragma unroll
    for (int mt = 0; mt < 2; mt++) {
        int r = wm * 32 + mt * 16 + (lid & 7) + ((lid >> 3) & 1) * 8;
        #pragma unroll
        for (int s = 0; s < 2; s++) {
            uint32_t c = (uint32_t)(s * 32 + ((lid >> 4) & 1) * 16);
            aOff[mt][s] = (uint32_t)(r * 64) + (c ^ (uint32_t)((r & 6) << 3));
        }
    }
    uint32_t bOff[4][2];
    #pragma unroll
    for (int ntp = 0; ntp < 4; ntp++) {
        int r = wn * 64 + ntp * 16 + (lid & 7) + ((lid >> 4) & 1) * 8;
        #pragma unroll
        for (int s = 0; s < 2; s++) {
            uint32_t c = (uint32_t)(s * 32 + ((lid >> 3) & 1) * 16);
            bOff[ntp][s] = (uint32_t)(r * 64) + (c ^ (uint32_t)((r & 6) << 3));
        }
    }

    // ---- load full A tile: 8 chunks x (128 rows x 64B), 4096 x 16B ----
    #pragma unroll
    for (int i = 0; i < 16; i++) {
        int idx = tid + i * 256;               // 0..4095
        int ck = idx >> 9;                     // chunk 0..7
        int r  = (idx >> 2) & 127;
        int c4 = idx & 3;
        uint32_t off = (uint32_t)(ck * 8192 + r * 64 + ((c4 * 16) ^ ((r & 6) << 3)));
        cp_async16(sA + off, g_xb + (rowBase + r) * DIM + ck * KCHUNK + c4 * 8);
    }
    CP_COMMIT();

    auto load_B = [&](int stage, int kc, int colBase) {
        uint32_t dst = sB + (uint32_t)stage * B_STAGE;
        #pragma unroll
        for (int i = 0; i < 2; i++) {
            int idx = tid + i * 256;           // 0..511
            int r = idx >> 2, c4 = idx & 3;
            uint32_t off = (uint32_t)(r * 64 + ((c4 * 16) ^ ((r & 6) << 3)));
            cp_async16(dst + off, Bsrc + (colBase + r) * DIM + kc * KCHUNK + c4 * 8);
        }
    };

    load_B(0, 0, colBaseGrp);                  // half 0, chunk 0
    CP_COMMIT();

    float c[2][8][4];
    #pragma unroll
    for (int mt = 0; mt < 2; mt++)
        #pragma unroll
        for (int nt = 0; nt < 8; nt++)
            #pragma unroll
            for (int k = 0; k < 4; k++) c[mt][nt][k] = 0.f;

    const float INV_TEMP = 1.0f / 0.3f;
    float tot[2][2] = {{0.f, 0.f}, {0.f, 0.f}};
    float pos[2][2] = {{0.f, 0.f}, {0.f, 0.f}};
    int rt[2][2];
    #pragma unroll
    for (int mt = 0; mt < 2; mt++)
        #pragma unroll
        for (int h = 0; h < 2; h++)
            rt[mt][h] = rowTidS[wm * 32 + mt * 16 + (lid >> 2) + 8 * h];

    #pragma unroll
    for (int half = 0; half < 2; half++) {
        const int colBase = colBaseGrp + half * BN;
        const bool diagBlk = isXX && (colBase == rowBase);

        #pragma unroll
        for (int kc = 0; kc < NCHUNK; kc++) {
            if (kc < NCHUNK - 1) {
                load_B((kc + 1) & 1, kc + 1, colBase);
                CP_COMMIT();
                CP_WAIT(1);
            } else if (half == 0) {
                load_B(0, 0, colBaseGrp + BN); // prefetch next half's chunk 0 into stage 0
                CP_COMMIT();
                CP_WAIT(1);
            } else {
                CP_WAIT(0);
            }
            __syncthreads();

            const uint32_t baseA = sA + (uint32_t)kc * 8192;
            const uint32_t baseB = sB + (uint32_t)(kc & 1) * B_STAGE;
            #pragma unroll
            for (int s = 0; s < 2; s++) {
                uint32_t a[2][4], b[4][4];
                ldsm4(a[0], baseA + aOff[0][s]);
                ldsm4(a[1], baseA + aOff[1][s]);
                #pragma unroll
                for (int ntp = 0; ntp < 4; ntp++) ldsm4(b[ntp], baseB + bOff[ntp][s]);
                #pragma unroll
                for (int mt = 0; mt < 2; mt++)
                    #pragma unroll
                    for (int nt = 0; nt < 8; nt++)
                        mma16816(c[mt][nt], a[mt], &b[nt >> 1][(nt & 1) * 2]);
            }
            __syncthreads();   // protect B stage from next iteration's overwrite
        }

        // ---- per-half epilogue: exp + accumulate row partials, then clear accs
        #pragma unroll
        for (int nt = 0; nt < 8; nt++) {
            const int colL = wn * 64 + nt * 8 + 2 * (lid & 3);
            const int ct0 = colTrkS[half * BN + colL];
            const int ct1 = colTrkS[half * BN + colL + 1];
            #pragma unroll
            for (int mt = 0; mt < 2; mt++)
                #pragma unroll
                for (int h = 0; h < 2; h++) {
                    float e0 = __expf(c[mt][nt][2 * h + 0] * INV_TEMP);
                    float e1 = __expf(c[mt][nt][2 * h + 1] * INV_TEMP);
                    tot[mt][h] += e0 + e1;
                    if (ct0 == rt[mt][h]) pos[mt][h] += e0;
                    if (ct1 == rt[mt][h]) pos[mt][h] += e1;
                    if (diagBlk) {
                        int rowg = rowBase + wm * 32 + mt * 16 + (lid >> 2) + 8 * h;
                        int colg = colBase + colL;
                        if (colg == rowg) g_diag[rowg] = e0;
                        if (colg + 1 == rowg) g_diag[rowg] = e1;
                    }
                    c[mt][nt][2 * h + 0] = 0.f;
                    c[mt][nt][2 * h + 1] = 0.f;
                }
        }
    }

    // ---- cross-warp row reduction, one write per (group, row) ----
    #pragma unroll
    for (int mt = 0; mt < 2; mt++)
        #pragma unroll
        for (int h = 0; h < 2; h++) {
            tot[mt][h] += __shfl_xor_sync(0xffffffffu, tot[mt][h], 1);
            tot[mt][h] += __shfl_xor_sync(0xffffffffu, tot[mt][h], 2);
            pos[mt][h] += __shfl_xor_sync(0xffffffffu, pos[mt][h], 1);
            pos[mt][h] += __shfl_xor_sync(0xffffffffu, pos[mt][h], 2);
        }

    if ((lid & 3) == 0) {
        #pragma unroll
        for (int mt = 0; mt < 2; mt++)
            #pragma unroll
            for (int h = 0; h < 2; h++) {
                int r = wm * 32 + mt * 16 + (lid >> 2) + 8 * h;
                redT[r * 2 + wn] = tot[mt][h];
                redP[r * 2 + wn] = pos[mt][h];
            }
    }
    __syncthreads();

    if (tid < BM) {
        g_tot[cg * N_ROWS + rowBase + tid] = redT[tid * 2] + redT[tid * 2 + 1];
        g_pos[cg * N_ROWS + rowBase + tid] = redP[tid * 2] + redP[tid * 2 + 1];
    }
}

// ---------------- Fused finalize + last-block final reduce --------------------
// 32 blocks x 256 threads; block b owns rows b*64..b*64+63.
__global__ __launch_bounds__(256)
void finalize_fused(const int* __restrict__ trk, float* __restrict__ out)
{
    __shared__ float sXT[4][64], sXP[4][64], sQT[4][64], sQP[4][64];
    __shared__ float sN[64], sD[64];
    __shared__ int   sT[64];
    __shared__ bool  isLast;

    const int r = threadIdx.x & 63;          // row in block
    const int g = threadIdx.x >> 6;          // tile group 0..3 (18 groups each)
    const int row = blockIdx.x * 64 + r;

    float xyT = 0.f, xyP = 0.f, xxT = 0.f, xxP = 0.f;
    #pragma unroll 2
    for (int c = g * 18; c < (g + 1) * 18; c++) {
        float t = g_tot[c * N_ROWS + row];
        float p = g_pos[c * N_ROWS + row];
        if (c < NGRP_XY) { xyT += t; xyP += p; }
        else             { xxT += t; xxP += p; }
    }
    sXT[g][r] = xyT; sXP[g][r] = xyP; sQT[g][r] = xxT; sQP[g][r] = xxP;
    __syncthreads();

    if (g == 0) {
        float aT = sXT[0][r] + sXT[1][r] + sXT[2][r] + sXT[3][r];
        float aP = sXP[0][r] + sXP[1][r] + sXP[2][r] + sXP[3][r];
        float bT = sQT[0][r] + sQT[1][r] + sQT[2][r] + sQT[3][r];
        float bP = sQP[0][r] + sQP[1][r] + sQP[2][r] + sQP[3][r];
        float dg = g_diag[row];
        sN[r] = aP + 0.5f * (bP - dg);
        sD[r] = (aT - aP) + (bT - bP);
        sT[r] = trk[row];
    }
    __syncthreads();

    // per-track partials over this block's 64 rows; thread = track id
    const int t = threadIdx.x;
    {
        float num = 0.f, den = 0.f; int cnt = 0;
        #pragma unroll 8
        for (int i = 0; i < 64; i++) {
            if (sT[i] == t) { num += sN[i]; den += sD[i]; cnt++; }
        }
        g_pnum[blockIdx.x * T_TRK + t] = num;
        g_pden[blockIdx.x * T_TRK + t] = den;
        g_pcnt[blockIdx.x * T_TRK + t] = cnt;
    }

    // ---- last block performs the global reduce ----
    __threadfence();
    if (threadIdx.x == 0) isLast = (atomicAdd(&g_tick, 1) == NCHNK_FIN - 1);
    __syncthreads();
    if (!isLast) return;

    float num = 0.f, den = 0.f; int cnt = 0;
    #pragma unroll
    for (int j = 0; j < NCHNK_FIN; j++) {
        num += g_pnum[j * T_TRK + t];
        den += g_pden[j * T_TRK + t];
        cnt += g_pcnt[j * T_TRK + t];
    }
    float loss = 0.f; int pres = 0;
    if (cnt > 0) { pres = 1; loss = -logf(num / (den + num)); }

    __shared__ float sL[T_TRK];
    __shared__ int   sP[T_TRK];
    sL[t] = loss; sP[t] = pres;
    __syncthreads();
    for (int s = T_TRK / 2; s > 0; s >>= 1) {
        if (t < s) { sL[t] += sL[t + s]; sP[t] += sP[t + s]; }
        __syncthreads();
    }
    if (t == 0) out[0] = sL[0] / (float)sP[0];
}

extern "C" void kernel_launch(void* const* d_in, const int* in_sizes, int n_in,
                              void* d_out, int out_size)
{
    const float* x   = (const float*)d_in[0];   // [2048, 256]
    const int*   trk = (const int*)  d_in[1];   // [2048]
    const float* y   = (const float*)d_in[2];   // [256, 64, 256]
    float* out = (float*)d_out;

    cudaFuncSetAttribute(gemm_mma, cudaFuncAttributeMaxDynamicSharedMemorySize, SMEM_BYTES);

    to_bf16_all<<<(NX4 + NY4 + 255) / 256, 256>>>(x, y);

    dim3 grid(N_ROWS / BM, NGRP);   // (16, 72)
    gemm_mma<<<grid, 256, SMEM_BYTES>>>(trk);
    finalize_fused<<<NCHNK_FIN, 256>>>(trk, out);
}

// round 8
// speedup vs baseline: 1.4911x; 1.4911x over previous
#include <cuda_runtime.h>
#include <cuda_bf16.h>
#include <cstdint>

// ---------------- Problem constants ----------------
#define N_ROWS   2048
#define DIM      256
#define T_TRK    256
#define NCOLS_XY 16384             // T*Q
#define BM       128
#define BN       128
#define NCT_XY   (NCOLS_XY / BN)   // 128
#define NCT_XX   (N_ROWS   / BN)   // 16
#define NCT_TOT  (NCT_XY + NCT_XX) // 144
#define KCHUNK   32                // bf16 per K chunk (64B rows)
#define NCHUNK   (DIM / KCHUNK)    // 8
#define NSTAGE   4
#define NCHNK_FIN 32               // finalize blocks (64 rows each)

// ---------------- Dynamic SMEM layout ----------------
#define A_STAGE  (BM * KCHUNK * 2)          // 8192
#define B_STAGE  (BN * KCHUNK * 2)          // 8192
#define OFF_A    0
#define OFF_B    (NSTAGE * A_STAGE)         // 32768
#define OFF_CTRK (OFF_B + NSTAGE * B_STAGE) // 65536
#define OFF_RTID (OFF_CTRK + BN * 4)        // 66048
#define OFF_REDT (OFF_RTID + BM * 4)        // 66560
#define OFF_REDP (OFF_REDT + BM * 2 * 4)    // 67584
#define SMEM_BYTES (OFF_REDP + BM * 2 * 4)  // 68608

// ---------------- Device scratch ----------------
static __device__ __nv_bfloat16 g_xb[N_ROWS * DIM];
static __device__ __nv_bfloat16 g_yb[NCOLS_XY * DIM];
static __device__ float g_tot[NCT_TOT * N_ROWS];
static __device__ float g_pos[NCT_TOT * N_ROWS];
static __device__ float g_diag[N_ROWS];
static __device__ float g_pnum[NCHNK_FIN * T_TRK];   // [chunk][track] coalesced
static __device__ float g_pden[NCHNK_FIN * T_TRK];
static __device__ int   g_pcnt[NCHNK_FIN * T_TRK];
static __device__ int   g_tick;

// ---------------- PTX helpers (baseline sm_80+, legal on plain sm_103) ----
__device__ __forceinline__ uint32_t smem_u32(const void* p) {
    uint32_t a;
    asm("{ .reg .u64 t; cvta.to.shared.u64 t, %1; cvt.u32.u64 %0, t; }" : "=r"(a) : "l"(p));
    return a;
}
__device__ __forceinline__ void cp_async16(uint32_t dst, const void* src) {
    asm volatile("cp.async.cg.shared.global [%0], [%1], 16;" :: "r"(dst), "l"(src));
}
#define CP_COMMIT() asm volatile("cp.async.commit_group;" ::: "memory")
#define CP_WAIT(n)  asm volatile("cp.async.wait_group %0;" :: "n"(n) : "memory")

__device__ __forceinline__ void ldsm4(uint32_t r[4], uint32_t addr) {
    asm volatile("ldmatrix.sync.aligned.m8n8.x4.shared.b16 {%0,%1,%2,%3}, [%4];"
                 : "=r"(r[0]), "=r"(r[1]), "=r"(r[2]), "=r"(r[3]) : "r"(addr));
}
__device__ __forceinline__ void mma16816(float c[4], const uint32_t a[4], const uint32_t b[2]) {
    asm volatile(
        "mma.sync.aligned.m16n8k16.row.col.f32.bf16.bf16.f32 "
        "{%0,%1,%2,%3}, {%4,%5,%6,%7}, {%8,%9}, {%0,%1,%2,%3};"
        : "+f"(c[0]), "+f"(c[1]), "+f"(c[2]), "+f"(c[3])
        : "r"(a[0]), "r"(a[1]), "r"(a[2]), "r"(a[3]), "r"(b[0]), "r"(b[1]));
}

// ---------------- fp32 -> bf16 conversion (2 float4 per thread) -------------
#define NX4 (N_ROWS * DIM / 4)      // 131072
#define NY4 (NCOLS_XY * DIM / 4)    // 1048576
#define NTOT4 (NX4 + NY4)           // 1179648
#define NHALF4 (NTOT4 / 2)          // 589824
__global__ void to_bf16_all(const float* __restrict__ x, const float* __restrict__ y)
{
    int i = blockIdx.x * blockDim.x + threadIdx.x;
    if (i == 0) g_tick = 0;                         // reset finalize ticket each call
    if (i >= NHALF4) return;
    #pragma unroll
    for (int h = 0; h < 2; h++) {
        int j = i + h * NHALF4;
        const float* s; __nv_bfloat16* d; int k;
        if (j < NX4) { s = x; d = g_xb; k = j; }
        else         { s = y; d = g_yb; k = j - NX4; }
        float4 v = reinterpret_cast<const float4*>(s)[k];
        __nv_bfloat162* o = reinterpret_cast<__nv_bfloat162*>(d);
        o[k * 2 + 0] = __floats2bfloat162_rn(v.x, v.y);
        o[k * 2 + 1] = __floats2bfloat162_rn(v.z, v.w);
    }
}

// ---------------- Fused HMMA GEMM + exp + row reductions ----------------
// grid (16, 144): blockIdx.y < 128 -> xy column tiles, >= 128 -> xx tiles.
// 128x128 tile, 256 threads, 2 CTAs/SM, 4-stage cp.async pipeline (1 sync/chunk).
__global__ __launch_bounds__(256, 2)
void gemm_mma(const int* __restrict__ trk)
{
    extern __shared__ char smem[];
    const uint32_t sA = smem_u32(smem) + OFF_A;
    const uint32_t sB = smem_u32(smem) + OFF_B;
    int*   colTrkS = (int*)(smem + OFF_CTRK);
    int*   rowTidS = (int*)(smem + OFF_RTID);
    float* redT    = (float*)(smem + OFF_REDT);
    float* redP    = (float*)(smem + OFF_REDP);

    const int tid = threadIdx.x;
    const int wid = tid >> 5;
    const int lid = tid & 31;
    const int wm = wid & 3;      // warp m: rows wm*32..+31
    const int wn = wid >> 2;     // warp n: cols wn*64..+63

    const int bx = blockIdx.x;
    const int ct = blockIdx.y;
    const bool isXX = (ct >= NCT_XY);
    const int rowBase = bx * BM;
    const int colBase = isXX ? (ct - NCT_XY) * BN : ct * BN;
    const __nv_bfloat16* Bsrc = isXX ? g_xb : g_yb;
    const bool diagBlk = isXX && (colBase == rowBase);

    if (tid < BN) colTrkS[tid] = isXX ? trk[colBase + tid] : ((colBase + tid) & (T_TRK - 1));
    if (tid < BM) rowTidS[tid] = trk[rowBase + tid];

    // ---- ldmatrix lane offsets (SW64 within each 8KB stage) ----
    uint32_t aOff[2][2];
    #pragma unroll
    for (int mt = 0; mt < 2; mt++) {
        int r = wm * 32 + mt * 16 + (lid & 7) + ((lid >> 3) & 1) * 8;
        #pragma unroll
        for (int s = 0; s < 2; s++) {
            uint32_t c = (uint32_t)(s * 32 + ((lid >> 4) & 1) * 16);
            aOff[mt][s] = (uint32_t)(r * 64) + (c ^ (uint32_t)((r & 6) << 3));
        }
    }
    uint32_t bOff[4][2];
    #pragma unroll
    for (int ntp = 0; ntp < 4; ntp++) {
        int r = wn * 64 + ntp * 16 + (lid & 7) + ((lid >> 4) & 1) * 8;
        #pragma unroll
        for (int s = 0; s < 2; s++) {
            uint32_t c = (uint32_t)(s * 32 + ((lid >> 3) & 1) * 16);
            bOff[ntp][s] = (uint32_t)(r * 64) + (c ^ (uint32_t)((r & 6) << 3));
        }
    }

    float c[2][8][4];
    #pragma unroll
    for (int mt = 0; mt < 2; mt++)
        #pragma unroll
        for (int nt = 0; nt < 8; nt++)
            #pragma unroll
            for (int k = 0; k < 4; k++) c[mt][nt][k] = 0.f;

    auto load_chunk = [&](int stage, int kc) {
        const int kEl = kc * KCHUNK;
        uint32_t dstA = sA + (uint32_t)stage * A_STAGE;
        uint32_t dstB = sB + (uint32_t)stage * B_STAGE;
        #pragma unroll
        for (int i = 0; i < 2; i++) {
            int idx = tid + i * 256;            // 0..511
            int r = idx >> 2, c4 = idx & 3;
            uint32_t off = (uint32_t)(r * 64 + ((c4 * 16) ^ ((r & 6) << 3)));
            cp_async16(dstA + off, g_xb + (rowBase + r) * DIM + kEl + c4 * 8);
            cp_async16(dstB + off, Bsrc + (colBase + r) * DIM + kEl + c4 * 8);
        }
    };

    // prologue: chunks 0 and 1 in flight
    load_chunk(0, 0); CP_COMMIT();
    load_chunk(1, 1); CP_COMMIT();

    // mainloop: issue chunk kc+2 into stage (kc+2)&3 (safe: that stage was last
    // read at compute kc-2, which barrier(kc-1) orders before this issue).
    #pragma unroll
    for (int kc = 0; kc < NCHUNK; kc++) {
        if (kc + 2 < NCHUNK) load_chunk((kc + 2) & (NSTAGE - 1), kc + 2);
        CP_COMMIT();           // empty group when nothing issued -> static wait count
        CP_WAIT(2);            // chunk kc complete (own groups); barrier makes it CTA-wide
        __syncthreads();

        const uint32_t baseA = sA + (uint32_t)(kc & (NSTAGE - 1)) * A_STAGE;
        const uint32_t baseB = sB + (uint32_t)(kc & (NSTAGE - 1)) * B_STAGE;
        #pragma unroll
        for (int s = 0; s < 2; s++) {
            uint32_t a[2][4], b[4][4];
            ldsm4(a[0], baseA + aOff[0][s]);
            ldsm4(a[1], baseA + aOff[1][s]);
            #pragma unroll
            for (int ntp = 0; ntp < 4; ntp++) ldsm4(b[ntp], baseB + bOff[ntp][s]);
            #pragma unroll
            for (int mt = 0; mt < 2; mt++)
                #pragma unroll
                for (int nt = 0; nt < 8; nt++)
                    mma16816(c[mt][nt], a[mt], &b[nt >> 1][(nt & 1) * 2]);
        }
    }

    // ---- epilogue: exp + track-matched row partials ----
    const float INV_TEMP = 1.0f / 0.3f;
    float tot[2][2] = {{0.f, 0.f}, {0.f, 0.f}};
    float pos[2][2] = {{0.f, 0.f}, {0.f, 0.f}};
    int rt[2][2];
    #pragma unroll
    for (int mt = 0; mt < 2; mt++)
        #pragma unroll
        for (int h = 0; h < 2; h++)
            rt[mt][h] = rowTidS[wm * 32 + mt * 16 + (lid >> 2) + 8 * h];

    #pragma unroll
    for (int nt = 0; nt < 8; nt++) {
        const int colL = wn * 64 + nt * 8 + 2 * (lid & 3);
        const int ct0 = colTrkS[colL], ct1 = colTrkS[colL + 1];
        #pragma unroll
        for (int mt = 0; mt < 2; mt++)
            #pragma unroll
            for (int h = 0; h < 2; h++) {
                float e0 = __expf(c[mt][nt][2 * h + 0] * INV_TEMP);
                float e1 = __expf(c[mt][nt][2 * h + 1] * INV_TEMP);
                tot[mt][h] += e0 + e1;
                if (ct0 == rt[mt][h]) pos[mt][h] += e0;
                if (ct1 == rt[mt][h]) pos[mt][h] += e1;
                if (diagBlk) {
                    int rowg = rowBase + wm * 32 + mt * 16 + (lid >> 2) + 8 * h;
                    int colg = colBase + colL;
                    if (colg == rowg) g_diag[rowg] = e0;
                    if (colg + 1 == rowg) g_diag[rowg] = e1;
                }
            }
    }

    #pragma unroll
    for (int mt = 0; mt < 2; mt++)
        #pragma unroll
        for (int h = 0; h < 2; h++) {
            tot[mt][h] += __shfl_xor_sync(0xffffffffu, tot[mt][h], 1);
            tot[mt][h] += __shfl_xor_sync(0xffffffffu, tot[mt][h], 2);
            pos[mt][h] += __shfl_xor_sync(0xffffffffu, pos[mt][h], 1);
            pos[mt][h] += __shfl_xor_sync(0xffffffffu, pos[mt][h], 2);
        }

    if ((lid & 3) == 0) {
        #pragma unroll
        for (int mt = 0; mt < 2; mt++)
            #pragma unroll
            for (int h = 0; h < 2; h++) {
                int r = wm * 32 + mt * 16 + (lid >> 2) + 8 * h;
                redT[r * 2 + wn] = tot[mt][h];
                redP[r * 2 + wn] = pos[mt][h];
            }
    }
    __syncthreads();

    if (tid < BM) {
        g_tot[ct * N_ROWS + rowBase + tid] = redT[tid * 2] + redT[tid * 2 + 1];
        g_pos[ct * N_ROWS + rowBase + tid] = redP[tid * 2] + redP[tid * 2 + 1];
    }
}

// ---------------- Fused finalize + last-block final reduce --------------------
// 32 blocks x 256 threads; block b owns rows b*64..b*64+63.
__global__ __launch_bounds__(256)
void finalize_fused(const int* __restrict__ trk, float* __restrict__ out)
{
    __shared__ float sXT[4][64], sXP[4][64], sQT[4][64], sQP[4][64];
    __shared__ float sN[64], sD[64];
    __shared__ int   sT[64];
    __shared__ bool  isLast;

    const int r = threadIdx.x & 63;          // row in block
    const int g = threadIdx.x >> 6;          // tile group 0..3 (36 tiles each)
    const int row = blockIdx.x * 64 + r;

    float xyT = 0.f, xyP = 0.f, xxT = 0.f, xxP = 0.f;
    #pragma unroll 4
    for (int c = g * 36; c < (g + 1) * 36; c++) {
        float t = g_tot[c * N_ROWS + row];
        float p = g_pos[c * N_ROWS + row];
        if (c < NCT_XY) { xyT += t; xyP += p; }
        else            { xxT += t; xxP += p; }
    }
    sXT[g][r] = xyT; sXP[g][r] = xyP; sQT[g][r] = xxT; sQP[g][r] = xxP;
    __syncthreads();

    if (g == 0) {
        float aT = sXT[0][r] + sXT[1][r] + sXT[2][r] + sXT[3][r];
        float aP = sXP[0][r] + sXP[1][r] + sXP[2][r] + sXP[3][r];
        float bT = sQT[0][r] + sQT[1][r] + sQT[2][r] + sQT[3][r];
        float bP = sQP[0][r] + sQP[1][r] + sQP[2][r] + sQP[3][r];
        float dg = g_diag[row];
        sN[r] = aP + 0.5f * (bP - dg);
        sD[r] = (aT - aP) + (bT - bP);
        sT[r] = trk[row];
    }
    __syncthreads();

    // per-track partials over this block's 64 rows; thread = track id
    const int t = threadIdx.x;
    {
        float num = 0.f, den = 0.f; int cnt = 0;
        #pragma unroll 8
        for (int i = 0; i < 64; i++) {
            if (sT[i] == t) { num += sN[i]; den += sD[i]; cnt++; }
        }
        g_pnum[blockIdx.x * T_TRK + t] = num;
        g_pden[blockIdx.x * T_TRK + t] = den;
        g_pcnt[blockIdx.x * T_TRK + t] = cnt;
    }

    // ---- last block performs the global reduce ----
    __threadfence();
    if (threadIdx.x == 0) isLast = (atomicAdd(&g_tick, 1) == NCHNK_FIN - 1);
    __syncthreads();
    if (!isLast) return;

    float num = 0.f, den = 0.f; int cnt = 0;
    #pragma unroll
    for (int j = 0; j < NCHNK_FIN; j++) {
        num += g_pnum[j * T_TRK + t];
        den += g_pden[j * T_TRK + t];
        cnt += g_pcnt[j * T_TRK + t];
    }
    float loss = 0.f; int pres = 0;
    if (cnt > 0) { pres = 1; loss = -logf(num / (den + num)); }

    __shared__ float sL[T_TRK];
    __shared__ int   sP[T_TRK];
    sL[t] = loss; sP[t] = pres;
    __syncthreads();
    for (int s = T_TRK / 2; s > 0; s >>= 1) {
        if (t < s) { sL[t] += sL[t + s]; sP[t] += sP[t + s]; }
        __syncthreads();
    }
    if (t == 0) out[0] = sL[0] / (float)sP[0];
}

extern "C" void kernel_launch(void* const* d_in, const int* in_sizes, int n_in,
                              void* d_out, int out_size)
{
    const float* x   = (const float*)d_in[0];   // [2048, 256]
    const int*   trk = (const int*)  d_in[1];   // [2048]
    const float* y   = (const float*)d_in[2];   // [256, 64, 256]
    float* out = (float*)d_out;

    cudaFuncSetAttribute(gemm_mma, cudaFuncAttributeMaxDynamicSharedMemorySize, SMEM_BYTES);

    to_bf16_all<<<(NHALF4 + 255) / 256, 256>>>(x, y);

    dim3 grid(N_ROWS / BM, NCT_TOT);   // (16, 144)
    gemm_mma<<<grid, 256, SMEM_BYTES>>>(trk);
    finalize_fused<<<NCHNK_FIN, 256>>>(trk, out);
}

// round 10
// speedup vs baseline: 1.5403x; 1.0330x over previous
#include <cuda_runtime.h>
#include <cuda_bf16.h>
#include <cstdint>

// ---------------- Problem constants ----------------
#define N_ROWS   2048
#define DIM      256
#define T_TRK    256
#define NCOLS_XY 16384             // T*Q
#define BM       128
#define BN       128
#define NCT_XY   (NCOLS_XY / BN)   // 128
#define NCT_XX   (N_ROWS   / BN)   // 16
#define NCT_TOT  (NCT_XY + NCT_XX) // 144
#define KCHUNK   64                // bf16 per K chunk (128B rows, SW128)
#define NCHUNK   (DIM / KCHUNK)    // 4
#define NSTAGE   3
#define NCHNK_FIN 32               // finalize blocks (64 rows each)

// ---------------- Dynamic SMEM layout ----------------
#define A_STAGE  (BM * KCHUNK * 2)          // 16384
#define B_STAGE  (BN * KCHUNK * 2)          // 16384
#define OFF_A    0
#define OFF_B    (NSTAGE * A_STAGE)         // 49152
#define OFF_CTRK (OFF_B + NSTAGE * B_STAGE) // 98304
#define OFF_RTID (OFF_CTRK + BN * 4)        // 98816
#define OFF_REDT (OFF_RTID + BM * 4)        // 99328
#define OFF_REDP (OFF_REDT + BM * 2 * 4)    // 100352
#define SMEM_BYTES (OFF_REDP + BM * 2 * 4)  // 101376 (~99KB, 2 CTAs = 198KB <= 228KB)

// ---------------- Device scratch ----------------
static __device__ __nv_bfloat16 g_xb[N_ROWS * DIM];
static __device__ __nv_bfloat16 g_yb[NCOLS_XY * DIM];
static __device__ float g_tot[NCT_TOT * N_ROWS];
static __device__ float g_pos[NCT_TOT * N_ROWS];
static __device__ float g_diag[N_ROWS];
static __device__ float g_pnum[NCHNK_FIN * T_TRK];   // [chunk][track] coalesced
static __device__ float g_pden[NCHNK_FIN * T_TRK];
static __device__ int   g_pcnt[NCHNK_FIN * T_TRK];
static __device__ int   g_tick;

// ---------------- PTX helpers (baseline sm_80+, legal on plain sm_103) ----
__device__ __forceinline__ uint32_t smem_u32(const void* p) {
    uint32_t a;
    asm("{ .reg .u64 t; cvta.to.shared.u64 t, %1; cvt.u32.u64 %0, t; }" : "=r"(a) : "l"(p));
    return a;
}
__device__ __forceinline__ void cp_async16(uint32_t dst, const void* src) {
    asm volatile("cp.async.cg.shared.global [%0], [%1], 16;" :: "r"(dst), "l"(src));
}
#define CP_COMMIT() asm volatile("cp.async.commit_group;" ::: "memory")
#define CP_WAIT(n)  asm volatile("cp.async.wait_group %0;" :: "n"(n) : "memory")

__device__ __forceinline__ void ldsm4(uint32_t r[4], uint32_t addr) {
    asm volatile("ldmatrix.sync.aligned.m8n8.x4.shared.b16 {%0,%1,%2,%3}, [%4];"
                 : "=r"(r[0]), "=r"(r[1]), "=r"(r[2]), "=r"(r[3]) : "r"(addr));
}
__device__ __forceinline__ void mma16816(float c[4], const uint32_t a[4], const uint32_t b[2]) {
    asm volatile(
        "mma.sync.aligned.m16n8k16.row.col.f32.bf16.bf16.f32 "
        "{%0,%1,%2,%3}, {%4,%5,%6,%7}, {%8,%9}, {%0,%1,%2,%3};"
        : "+f"(c[0]), "+f"(c[1]), "+f"(c[2]), "+f"(c[3])
        : "r"(a[0]), "r"(a[1]), "r"(a[2]), "r"(a[3]), "r"(b[0]), "r"(b[1]));
}

// ---------------- fp32 -> bf16 conversion (4 float4 per thread) -------------
#define NX4 (N_ROWS * DIM / 4)      // 131072
#define NY4 (NCOLS_XY * DIM / 4)    // 1048576
#define NTOT4 (NX4 + NY4)           // 1179648
#define NQ4   (NTOT4 / 4)           // 294912
__global__ void to_bf16_all(const float* __restrict__ x, const float* __restrict__ y)
{
    int i = blockIdx.x * blockDim.x + threadIdx.x;
    if (i == 0) g_tick = 0;                         // reset finalize ticket each call
    if (i >= NQ4) return;
    #pragma unroll
    for (int h = 0; h < 4; h++) {
        int j = i + h * NQ4;
        const float* s; __nv_bfloat16* d; int k;
        if (j < NX4) { s = x; d = g_xb; k = j; }
        else         { s = y; d = g_yb; k = j - NX4; }
        float4 v = reinterpret_cast<const float4*>(s)[k];
        __nv_bfloat162* o = reinterpret_cast<__nv_bfloat162*>(d);
        o[k * 2 + 0] = __floats2bfloat162_rn(v.x, v.y);
        o[k * 2 + 1] = __floats2bfloat162_rn(v.z, v.w);
    }
}

// ---------------- Fused HMMA GEMM + exp + row reductions ----------------
// grid (16, 144): blockIdx.y < 128 -> xy column tiles, >= 128 -> xx tiles.
// 128x128 tile, 256 threads, 2 CTAs/SM, K=64 chunks, 3-stage pipeline,
// one __syncthreads per chunk (sync BEFORE next load issue -> hazard-free).
__global__ __launch_bounds__(256, 2)
void gemm_mma(const int* __restrict__ trk)
{
    extern __shared__ char smem[];
    const uint32_t sA = smem_u32(smem) + OFF_A;
    const uint32_t sB = smem_u32(smem) + OFF_B;
    int*   colTrkS = (int*)(smem + OFF_CTRK);
    int*   rowTidS = (int*)(smem + OFF_RTID);
    float* redT    = (float*)(smem + OFF_REDT);
    float* redP    = (float*)(smem + OFF_REDP);

    const int tid = threadIdx.x;
    const int wid = tid >> 5;
    const int lid = tid & 31;
    const int wm = wid & 3;      // warp m: rows wm*32..+31
    const int wn = wid >> 2;     // warp n: cols wn*64..+63

    const int bx = blockIdx.x;
    const int ct = blockIdx.y;
    const bool isXX = (ct >= NCT_XY);
    const int rowBase = bx * BM;
    const int colBase = isXX ? (ct - NCT_XY) * BN : ct * BN;
    const __nv_bfloat16* Bsrc = isXX ? g_xb : g_yb;
    const bool diagBlk = isXX && (colBase == rowBase);

    if (tid < BN) colTrkS[tid] = isXX ? trk[colBase + tid] : ((colBase + tid) & (T_TRK - 1));
    if (tid < BM) rowTidS[tid] = trk[rowBase + tid];

    // ---- ldmatrix base offsets at K-step 0 (SW128: c16 ^ (r&7)) ----
    // step s offsets are XOR-additive: off(s) = off(0) ^ (s << 5)
    uint32_t aOff0[2];
    #pragma unroll
    for (int mt = 0; mt < 2; mt++) {
        int r = wm * 32 + mt * 16 + (lid & 7) + ((lid >> 3) & 1) * 8;
        uint32_t c16 = (uint32_t)((lid >> 4) & 1);
        aOff0[mt] = (uint32_t)(r * 128) + ((c16 ^ (uint32_t)(r & 7)) * 16);
    }
    uint32_t bOff0[4];
    #pragma unroll
    for (int ntp = 0; ntp < 4; ntp++) {
        int r = wn * 64 + ntp * 16 + (lid & 7) + ((lid >> 4) & 1) * 8;
        uint32_t c16 = (uint32_t)((lid >> 3) & 1);
        bOff0[ntp] = (uint32_t)(r * 128) + ((c16 ^ (uint32_t)(r & 7)) * 16);
    }

    float c[2][8][4];
    #pragma unroll
    for (int mt = 0; mt < 2; mt++)
        #pragma unroll
        for (int nt = 0; nt < 8; nt++)
            #pragma unroll
            for (int k = 0; k < 4; k++) c[mt][nt][k] = 0.f;

    // per chunk: A = 128 rows x 128B = 1024x16B, B same -> 4+4 cp.async/thread
    auto load_chunk = [&](int stage, int kc) {
        const int kEl = kc * KCHUNK;
        uint32_t dstA = sA + (uint32_t)stage * A_STAGE;
        uint32_t dstB = sB + (uint32_t)stage * B_STAGE;
        #pragma unroll
        for (int i = 0; i < 4; i++) {
            int idx = tid + i * 256;            // 0..1023
            int r = idx >> 3, c8 = idx & 7;
            uint32_t off = (uint32_t)(r * 128) + (((uint32_t)c8 ^ (uint32_t)(r & 7)) * 16);
            cp_async16(dstA + off, g_xb + (rowBase + r) * DIM + kEl + c8 * 8);
            cp_async16(dstB + off, Bsrc + (colBase + r) * DIM + kEl + c8 * 8);
        }
    };

    // prologue: chunks 0 and 1 in flight
    load_chunk(0, 0); CP_COMMIT();
    load_chunk(1, 1); CP_COMMIT();

    #pragma unroll
    for (int kc = 0; kc < NCHUNK; kc++) {
        if (kc == NCHUNK - 1) { CP_WAIT(0); } else { CP_WAIT(1); }  // chunk kc arrived
        __syncthreads();                       // CTA-wide visibility; orders compute(kc-1)
        if (kc + 2 < NCHUNK) {                 // refill stage (kc+2)%3 == (kc-1)%3, now free
            load_chunk((kc + 2) % NSTAGE, kc + 2);
            CP_COMMIT();
        }

        const uint32_t baseA = sA + (uint32_t)(kc % NSTAGE) * A_STAGE;
        const uint32_t baseB = sB + (uint32_t)(kc % NSTAGE) * B_STAGE;
        #pragma unroll
        for (int s = 0; s < 4; s++) {
            const uint32_t sx = (uint32_t)(s << 5);
            uint32_t a[2][4], b[4][4];
            ldsm4(a[0], baseA + (aOff0[0] ^ sx));
            ldsm4(a[1], baseA + (aOff0[1] ^ sx));
            #pragma unroll
            for (int ntp = 0; ntp < 4; ntp++) ldsm4(b[ntp], baseB + (bOff0[ntp] ^ sx));
            #pragma unroll
            for (int mt = 0; mt < 2; mt++)
                #pragma unroll
                for (int nt = 0; nt < 8; nt++)
                    mma16816(c[mt][nt], a[mt], &b[nt >> 1][(nt & 1) * 2]);
        }
    }

    // ---- epilogue: exp + track-matched row partials ----
    const float INV_TEMP = 1.0f / 0.3f;
    float tot[2][2] = {{0.f, 0.f}, {0.f, 0.f}};
    float pos[2][2] = {{0.f, 0.f}, {0.f, 0.f}};
    int rt[2][2];
    #pragma unroll
    for (int mt = 0; mt < 2; mt++)
        #pragma unroll
        for (int h = 0; h < 2; h++)
            rt[mt][h] = rowTidS[wm * 32 + mt * 16 + (lid >> 2) + 8 * h];

    #pragma unroll
    for (int nt = 0; nt < 8; nt++) {
        const int colL = wn * 64 + nt * 8 + 2 * (lid & 3);
        const int ct0 = colTrkS[colL], ct1 = colTrkS[colL + 1];
        #pragma unroll
        for (int mt = 0; mt < 2; mt++)
            #pragma unroll
            for (int h = 0; h < 2; h++) {
                float e0 = __expf(c[mt][nt][2 * h + 0] * INV_TEMP);
                float e1 = __expf(c[mt][nt][2 * h + 1] * INV_TEMP);
                tot[mt][h] += e0 + e1;
                if (ct0 == rt[mt][h]) pos[mt][h] += e0;
                if (ct1 == rt[mt][h]) pos[mt][h] += e1;
                if (diagBlk) {
                    int rowg = rowBase + wm * 32 + mt * 16 + (lid >> 2) + 8 * h;
                    int colg = colBase + colL;
                    if (colg == rowg) g_diag[rowg] = e0;
                    if (colg + 1 == rowg) g_diag[rowg] = e1;
                }
            }
    }

    #pragma unroll
    for (int mt = 0; mt < 2; mt++)
        #pragma unroll
        for (int h = 0; h < 2; h++) {
            tot[mt][h] += __shfl_xor_sync(0xffffffffu, tot[mt][h], 1);
            tot[mt][h] += __shfl_xor_sync(0xffffffffu, tot[mt][h], 2);
            pos[mt][h] += __shfl_xor_sync(0xffffffffu, pos[mt][h], 1);
            pos[mt][h] += __shfl_xor_sync(0xffffffffu, pos[mt][h], 2);
        }

    if ((lid & 3) == 0) {
        #pragma unroll
        for (int mt = 0; mt < 2; mt++)
            #pragma unroll
            for (int h = 0; h < 2; h++) {
                int r = wm * 32 + mt * 16 + (lid >> 2) + 8 * h;
                redT[r * 2 + wn] = tot[mt][h];
                redP[r * 2 + wn] = pos[mt][h];
            }
    }
    __syncthreads();

    if (tid < BM) {
        g_tot[ct * N_ROWS + rowBase + tid] = redT[tid * 2] + redT[tid * 2 + 1];
        g_pos[ct * N_ROWS + rowBase + tid] = redP[tid * 2] + redP[tid * 2 + 1];
    }
}

// ---------------- Fused finalize + last-block final reduce --------------------
// 32 blocks x 256 threads; block b owns rows b*64..b*64+63.
__global__ __launch_bounds__(256)
void finalize_fused(const int* __restrict__ trk, float* __restrict__ out)
{
    __shared__ float sXT[4][64], sXP[4][64], sQT[4][64], sQP[4][64];
    __shared__ float sN[64], sD[64];
    __shared__ int   sT[64];
    __shared__ bool  isLast;

    const int r = threadIdx.x & 63;          // row in block
    const int g = threadIdx.x >> 6;          // tile group 0..3 (36 tiles each)
    const int row = blockIdx.x * 64 + r;

    float xyT = 0.f, xyP = 0.f, xxT = 0.f, xxP = 0.f;
    #pragma unroll 4
    for (int c = g * 36; c < (g + 1) * 36; c++) {
        float t = g_tot[c * N_ROWS + row];
        float p = g_pos[c * N_ROWS + row];
        if (c < NCT_XY) { xyT += t; xyP += p; }
        else            { xxT += t; xxP += p; }
    }
    sXT[g][r] = xyT; sXP[g][r] = xyP; sQT[g][r] = xxT; sQP[g][r] = xxP;
    __syncthreads();

    if (g == 0) {
        float aT = sXT[0][r] + sXT[1][r] + sXT[2][r] + sXT[3][r];
        float aP = sXP[0][r] + sXP[1][r] + sXP[2][r] + sXP[3][r];
        float bT = sQT[0][r] + sQT[1][r] + sQT[2][r] + sQT[3][r];
        float bP = sQP[0][r] + sQP[1][r] + sQP[2][r] + sQP[3][r];
        float dg = g_diag[row];
        sN[r] = aP + 0.5f * (bP - dg);
        sD[r] = (aT - aP) + (bT - bP);
        sT[r] = trk[row];
    }
    __syncthreads();

    // per-track partials over this block's 64 rows; thread = track id
    const int t = threadIdx.x;
    {
        float num = 0.f, den = 0.f; int cnt = 0;
        #pragma unroll 8
        for (int i = 0; i < 64; i++) {
            if (sT[i] == t) { num += sN[i]; den += sD[i]; cnt++; }
        }
        g_pnum[blockIdx.x * T_TRK + t] = num;
        g_pden[blockIdx.x * T_TRK + t] = den;
        g_pcnt[blockIdx.x * T_TRK + t] = cnt;
    }

    // ---- last block performs the global reduce ----
    __threadfence();
    if (threadIdx.x == 0) isLast = (atomicAdd(&g_tick, 1) == NCHNK_FIN - 1);
    __syncthreads();
    if (!isLast) return;

    float num = 0.f, den = 0.f; int cnt = 0;
    #pragma unroll
    for (int j = 0; j < NCHNK_FIN; j++) {
        num += g_pnum[j * T_TRK + t];
        den += g_pden[j * T_TRK + t];
        cnt += g_pcnt[j * T_TRK + t];
    }
    float loss = 0.f; int pres = 0;
    if (cnt > 0) { pres = 1; loss = -logf(num / (den + num)); }

    __shared__ float sL[T_TRK];
    __shared__ int   sP[T_TRK];
    sL[t] = loss; sP[t] = pres;
    __syncthreads();
    for (int s = T_TRK / 2; s > 0; s >>= 1) {
        if (t < s) { sL[t] += sL[t + s]; sP[t] += sP[t + s]; }
        __syncthreads();
    }
    if (t == 0) out[0] = sL[0] / (float)sP[0];
}

extern "C" void kernel_launch(void* const* d_in, const int* in_sizes, int n_in,
                              void* d_out, int out_size)
{
    const float* x   = (const float*)d_in[0];   // [2048, 256]
    const int*   trk = (const int*)  d_in[1];   // [2048]
    const float* y   = (const float*)d_in[2];   // [256, 64, 256]
    float* out = (float*)d_out;

    cudaFuncSetAttribute(gemm_mma, cudaFuncAttributeMaxDynamicSharedMemorySize, SMEM_BYTES);

    to_bf16_all<<<(NQ4 + 255) / 256, 256>>>(x, y);

    dim3 grid(N_ROWS / BM, NCT_TOT);   // (16, 144)
    gemm_mma<<<grid, 256, SMEM_BYTES>>>(trk);
    finalize_fused<<<NCHNK_FIN, 256>>>(trk, out);
}